// round 17
// baseline (speedup 1.0000x reference)
#include <cuda_runtime.h>

#define NQ     10
#define NL     4
#define WPB    4
#define BLOCK  (32 * WPB)

typedef unsigned long long u64;

// Per gate: 6 SPLAT packs {Car,Cai,CaiN,Cbr,Cbi,CbrN} with a=M00, b=M10 (SU2)
__device__   u64 gPackedBuf[NL * NQ * 6];
__constant__ u64 cG[NL * NQ * 6];
// Layer-0 fused matrices, plain floats: {M00x,M00y,M01x,M01y,M10x,M10y,M11x,M11y}
__device__   float gM0Buf[NQ * 8];
__constant__ float cM0[NQ * 8];

// ============================================================
// Compile-time GF(2) frame tables (semantics verified R8-R16)
// ============================================================
__host__ __device__ constexpr int parc(int v) {
    int c = 0;
    for (int b = 0; b < NQ; ++b) c ^= (v >> b) & 1;
    return c;
}

constexpr int sigma1(int j) {
    int s = j;
    for (int q = 9; q >= 0; --q) {
        int pc = 9 - q;
        int pt = 9 - ((q + 1) % 10);
        s ^= ((s >> pc) & 1) << pt;
    }
    return s;
}

struct MaskTab {
    int m[NL][NQ];
    int sel[NL + 1][NQ];
};

constexpr MaskTab build_masks() {
    MaskTab t{};
    int perm[1024] = {};
    for (int j = 0; j < 1024; ++j) perm[j] = j;
    int inv[1024] = {};
    for (int l = 0; l <= NL; ++l) {
        if (l < NL)
            for (int p = 0; p < NQ; ++p) t.m[l][p] = perm[1 << p];
        for (int j = 0; j < 1024; ++j) inv[perm[j]] = j;
        for (int p = 0; p < NQ; ++p) {
            int s = 0;
            for (int b = 0; b < NQ; ++b) s |= ((inv[1 << b] >> p) & 1) << b;
            t.sel[l][p] = s;
        }
        if (l < NL) {
            int nxt[1024] = {};
            for (int j = 0; j < 1024; ++j) nxt[j] = perm[sigma1(j)];
            for (int j = 0; j < 1024; ++j) perm[j] = nxt[j];
        }
    }
    return t;
}
constexpr MaskTab MT = build_masks();

// Sign mask for pack index J of parity functional (creg, cp):
// bit31 iff parity of lo-amp, bit63 iff parity of hi-amp.
__host__ __device__ constexpr u64 kmask_sign(int creg, int cp, int J) {
    int lo = parc(J & creg);
    int hi = lo ^ (cp & 1);
    return (lo ? 0x80000000ull : 0ull) | (hi ? 0x8000000000000000ull : 0ull);
}
__host__ __device__ constexpr u64 swapc(u64 v) { return (v >> 32) | (v << 32); }
constexpr u64 SGNC = 0x8000000080000000ull;

// ============================================================
// Packed f32x2 helpers
// ============================================================
__device__ __forceinline__ u64 pk2(float a, float b) {
    u64 r; asm("mov.b64 %0, {%1, %2};" : "=l"(r) : "f"(a), "f"(b)); return r;
}
__device__ __forceinline__ void upk(u64 v, float& a, float& b) {
    asm("mov.b64 {%0, %1}, %2;" : "=f"(a), "=f"(b) : "l"(v));
}
__device__ __forceinline__ u64 fma2(u64 a, u64 b, u64 c) {
    u64 d; asm("fma.rn.f32x2 %0, %1, %2, %3;" : "=l"(d) : "l"(a), "l"(b), "l"(c)); return d;
}
__device__ __forceinline__ u64 mul2(u64 a, u64 b) {
    u64 d; asm("mul.rn.f32x2 %0, %1, %2;" : "=l"(d) : "l"(a), "l"(b)); return d;
}
__device__ __forceinline__ u64 swap64(u64 v) {
    union { u64 w; uint2 u; } a;
    a.w = v;
    unsigned t = a.u.x; a.u.x = a.u.y; a.u.y = t;
    return a.w;
}
__device__ __forceinline__ u64 shfl64x(u64 v, int xm) {
    return __shfl_xor_sync(0xffffffffu, v, xm);
}

// ============================================================
// Setup: fuse Rx*Ry*Rz; SU2 splat packs + raw M for layer 0
// ============================================================
struct c2 { float x, y; };
__device__ __forceinline__ c2 cmulh(c2 a, c2 b) { return { a.x*b.x - a.y*b.y, a.x*b.y + a.y*b.x }; }
__device__ __forceinline__ c2 caddh(c2 a, c2 b) { return { a.x + b.x, a.y + b.y }; }

__global__ void tq_setup_kernel(const float* __restrict__ theta) {
    int t = threadIdx.x;
    if (t >= NL * NQ) return;
    float t0 = theta[t*3+0], t1 = theta[t*3+1], t2 = theta[t*3+2];
    float cx = cosf(0.5f*t0), sx = sinf(0.5f*t0);
    float cy = cosf(0.5f*t1), sy = sinf(0.5f*t1);
    float cz = cosf(0.5f*t2), sz = sinf(0.5f*t2);

    c2 x00{cx,0.f}, x01{0.f,-sx}, x10{0.f,-sx}, x11{cx,0.f};
    c2 y00{cy,0.f}, y01{-sy,0.f}, y10{sy,0.f},  y11{cy,0.f};

    c2 A00 = caddh(cmulh(x00,y00), cmulh(x01,y10));
    c2 A01 = caddh(cmulh(x00,y01), cmulh(x01,y11));
    c2 A10 = caddh(cmulh(x10,y00), cmulh(x11,y10));
    c2 A11 = caddh(cmulh(x10,y01), cmulh(x11,y11));

    c2 e0{cz,-sz}, e1{cz,sz};
    c2 M00 = cmulh(A00,e0), M01 = cmulh(A01,e1);
    c2 M10 = cmulh(A10,e0), M11 = cmulh(A11,e1);

    u64* o = &gPackedBuf[t * 6];
    o[0] = pk2(M00.x,  M00.x);   // Car
    o[1] = pk2(M00.y,  M00.y);   // Cai
    o[2] = pk2(-M00.y, -M00.y);  // CaiN
    o[3] = pk2(M10.x,  M10.x);   // Cbr
    o[4] = pk2(M10.y,  M10.y);   // Cbi
    o[5] = pk2(-M10.x, -M10.x);  // CbrN

    if (t < NQ) {
        float* m = &gM0Buf[t * 8];
        m[0] = M00.x; m[1] = M00.y; m[2] = M01.x; m[3] = M01.y;
        m[4] = M10.x; m[5] = M10.y; m[6] = M11.x; m[7] = M11.y;
    }
}

// ============================================================
// Gate, gauge form, ys in SMEM (double-buffered rd -> wr).
// Stored ys gauge = sel of previous gate (chain SELPREV).
// All gauge/eps corrections fold into one XOR mask per value:
//  own   : raw ^ (KD(J) ^ bmD)
//  partner(dest J from slot Jp): swap?(raw) ^ (swapc?(KD(Jp)) ^ dlmS ^ KS(J) ^ bmD ^ bmS)
// matching R16's verified "regauge-in-place, move, eps" order.
// ============================================================
#define KDJ(J) kmask_sign(Dreg, Dp, (J))
#define KSJ(J) kmask_sign(selreg, sp, (J))

#define G3_SELF(J) {                                                          \
    constexpr u64 MOWN  = KDJ(J);                                             \
    constexpr u64 MPART = (mp ? swapc(KDJ(J)) : KDJ(J))                       \
                          ^ (dlm ? SGNC : 0ull) ^ KSJ(J);                     \
    u64 raw = rd[(J)*32 + lane];                                              \
    u64 praw = raw;                                                           \
    if constexpr (mlane != 0) praw = rd[(J)*32 + (lane ^ mlane)];             \
    u64 yown = raw ^ (MOWN ^ bmD);                                            \
    u64 py = praw;                                                            \
    if constexpr (mp) py = swap64(py);                                        \
    py ^= (MPART ^ bmD ^ bmS);                                                \
    u64 px = xs[J];                                                           \
    if constexpr (mlane != 0) px = shfl64x(px, mlane);                        \
    if constexpr (mp) px = swap64(px);                                        \
    px ^= (bmS ^ KSJ(J));                                                     \
    u64 nx = fma2(py, Cbi,  fma2(px, Cbr, fma2(yown, CaiN, mul2(xs[J], Car)))); \
    u64 ny = fma2(py, CbrN, fma2(px, Cbi, fma2(yown, Car,  mul2(xs[J], Cai)))); \
    xs[J] = nx;  wr[(J)*32 + lane] = ny; }

#define G3_PAIR(J) if constexpr ((((J) & hb) == 0) && mreg != 0) {            \
    constexpr int J2_ = (J) ^ mreg;                                           \
    constexpr u64 MOA = KDJ(J);                                               \
    constexpr u64 MOB = KDJ(J2_);                                             \
    constexpr u64 MPA = (mp ? swapc(KDJ(J2_)) : KDJ(J2_))                     \
                        ^ (dlm ? SGNC : 0ull) ^ KSJ(J);                       \
    constexpr u64 MPB = (mp ? swapc(KDJ(J)) : KDJ(J))                         \
                        ^ (dlm ? SGNC : 0ull) ^ KSJ(J2_);                     \
    u64 rawA = rd[(J)*32 + lane], rawB = rd[J2_*32 + lane];                   \
    u64 prA, prB;                                                             \
    if constexpr (mlane != 0) { prA = rd[J2_*32 + (lane ^ mlane)];            \
                                prB = rd[(J)*32 + (lane ^ mlane)]; }          \
    else                      { prA = rawB; prB = rawA; }                     \
    u64 yA = rawA ^ (MOA ^ bmD);                                              \
    u64 yB = rawB ^ (MOB ^ bmD);                                              \
    if constexpr (mp) { prA = swap64(prA); prB = swap64(prB); }               \
    u64 payv = prA ^ (MPA ^ bmD ^ bmS);                                       \
    u64 pbyv = prB ^ (MPB ^ bmD ^ bmS);                                       \
    u64 pax = xs[J2_], pbx = xs[J];                                           \
    if constexpr (mlane != 0) { pax = shfl64x(pax, mlane);                    \
                                pbx = shfl64x(pbx, mlane); }                  \
    if constexpr (mp) { pax = swap64(pax); pbx = swap64(pbx); }               \
    pax ^= (bmS ^ KSJ(J));                                                    \
    pbx ^= (bmS ^ KSJ(J2_));                                                  \
    u64 nxa = fma2(payv, Cbi,  fma2(pax, Cbr, fma2(yA, CaiN, mul2(xs[J],  Car)))); \
    u64 nya = fma2(payv, CbrN, fma2(pax, Cbi, fma2(yA, Car,  mul2(xs[J],  Cai)))); \
    u64 nxb = fma2(pbyv, Cbi,  fma2(pbx, Cbr, fma2(yB, CaiN, mul2(xs[J2_], Car)))); \
    u64 nyb = fma2(pbyv, CbrN, fma2(pbx, Cbi, fma2(yB, Car,  mul2(xs[J2_], Cai)))); \
    xs[J] = nxa; xs[J2_] = nxb;                                               \
    wr[(J)*32 + lane] = nya;  wr[J2_*32 + lane] = nyb; }

template<int SELPREV, int L, int P>
__device__ __forceinline__ void gate2(u64* xs, const u64* rd, u64* wr, int lane) {
    constexpr int m  = MT.m[L][P];
    constexpr int sl = MT.sel[L][P];
    static_assert(parc(m & sl) == 1, "pair must flip role");
    constexpr int mp = (m >> 9) & 1, mreg = (m >> 5) & 15, mlane = m & 31;
    constexpr int sp = (sl >> 9) & 1, selreg = (sl >> 5) & 15, sellane = sl & 31;
    constexpr int D  = sl ^ SELPREV;
    constexpr int Dp = (D >> 9) & 1, Dreg = (D >> 5) & 15, Dlane = D & 31;
    constexpr int dlm = parc(Dlane & mlane);
    constexpr int g6 = (L * NQ + (9 - P)) * 6;
    constexpr int hb = mreg ? (mreg & (-mreg)) : 1;

    __syncwarp();   // previous gate's smem writes -> this gate's reads

    const u64 Car  = cG[g6+0], Cai  = cG[g6+1], CaiN = cG[g6+2];
    const u64 Cbr  = cG[g6+3], Cbi  = cG[g6+4], CbrN = cG[g6+5];

    u64 bmD = 0;
    if constexpr (Dlane != 0)
        bmD = (__popc(lane & Dlane) & 1) ? SGNC : 0ull;
    u64 bmS = 0;
    if constexpr (sellane != 0)
        bmS = (__popc(lane & sellane) & 1) ? SGNC : 0ull;

    if constexpr (mreg == 0) {
        G3_SELF(0)  G3_SELF(1)  G3_SELF(2)  G3_SELF(3)
        G3_SELF(4)  G3_SELF(5)  G3_SELF(6)  G3_SELF(7)
        G3_SELF(8)  G3_SELF(9)  G3_SELF(10) G3_SELF(11)
        G3_SELF(12) G3_SELF(13) G3_SELF(14) G3_SELF(15)
    } else {
        G3_PAIR(0)  G3_PAIR(1)  G3_PAIR(2)  G3_PAIR(3)
        G3_PAIR(4)  G3_PAIR(5)  G3_PAIR(6)  G3_PAIR(7)
        G3_PAIR(8)  G3_PAIR(9)  G3_PAIR(10) G3_PAIR(11)
        G3_PAIR(12) G3_PAIR(13) G3_PAIR(14) G3_PAIR(15)
    }
}

// R13 interleaved order, gauge chained; banks alternate per gate.
__device__ __forceinline__ void run_layers(u64* xs, u64* b0, u64* b1, int lane) {
    gate2<0,            1, 5>(xs, b0, b1, lane);
    gate2<MT.sel[1][5], 1, 9>(xs, b1, b0, lane);
    gate2<MT.sel[1][9], 1, 4>(xs, b0, b1, lane);
    gate2<MT.sel[1][4], 1, 8>(xs, b1, b0, lane);
    gate2<MT.sel[1][8], 1, 3>(xs, b0, b1, lane);
    gate2<MT.sel[1][3], 1, 7>(xs, b1, b0, lane);
    gate2<MT.sel[1][7], 1, 2>(xs, b0, b1, lane);
    gate2<MT.sel[1][2], 1, 6>(xs, b1, b0, lane);
    gate2<MT.sel[1][6], 1, 1>(xs, b0, b1, lane);
    gate2<MT.sel[1][1], 1, 0>(xs, b1, b0, lane);

    gate2<MT.sel[1][0], 2, 6>(xs, b0, b1, lane);
    gate2<MT.sel[2][6], 2, 9>(xs, b1, b0, lane);
    gate2<MT.sel[2][9], 2, 5>(xs, b0, b1, lane);
    gate2<MT.sel[2][5], 2, 8>(xs, b1, b0, lane);
    gate2<MT.sel[2][8], 2, 4>(xs, b0, b1, lane);
    gate2<MT.sel[2][4], 2, 7>(xs, b1, b0, lane);
    gate2<MT.sel[2][7], 2, 3>(xs, b0, b1, lane);
    gate2<MT.sel[2][3], 2, 2>(xs, b1, b0, lane);
    gate2<MT.sel[2][2], 2, 1>(xs, b0, b1, lane);
    gate2<MT.sel[2][1], 2, 0>(xs, b1, b0, lane);

    gate2<MT.sel[2][0], 3, 7>(xs, b0, b1, lane);
    gate2<MT.sel[3][7], 3, 9>(xs, b1, b0, lane);
    gate2<MT.sel[3][9], 3, 6>(xs, b0, b1, lane);
    gate2<MT.sel[3][6], 3, 8>(xs, b1, b0, lane);
    gate2<MT.sel[3][8], 3, 5>(xs, b0, b1, lane);
    gate2<MT.sel[3][5], 3, 4>(xs, b1, b0, lane);
    gate2<MT.sel[3][4], 3, 3>(xs, b0, b1, lane);
    gate2<MT.sel[3][3], 3, 2>(xs, b1, b0, lane);
    gate2<MT.sel[3][2], 3, 1>(xs, b0, b1, lane);
    gate2<MT.sel[3][1], 3, 0>(xs, b1, b0, lane);   // final ys in b0
}

// ============================================================
// Readout (unchanged; probabilities are gauge-free)
// ============================================================
template<int Q>
__device__ __forceinline__ float readout_one(const u64* pr, int lane) {
    constexpr int sel = MT.sel[NL][9 - Q];
    constexpr int sp  = (sel >> 9) & 1;
    constexpr int sr  = (sel >> 5) & 15;
    constexpr int slq = sel & 31;
    const u64 sPP = pk2(1.f,  sp ? -1.f : 1.f);
    const u64 sNN = pk2(-1.f, sp ? 1.f : -1.f);
    u64 acc = pk2(0.f, 0.f);
#pragma unroll
    for (int j = 0; j < 16; ++j)
        acc = fma2(pr[j], parc(j & sr) ? sNN : sPP, acc);
    float lo, hi; upk(acc, lo, hi);
    float a = lo + hi;
    if constexpr (slq != 0) {
        if (__popc(lane & slq) & 1) a = -a;
    }
#pragma unroll
    for (int off = 16; off; off >>= 1)
        a += __shfl_xor_sync(0xffffffffu, a, off);
    return a;
}

// ============================================================
// Main kernel: xs in regs, ys in double-buffered smem; 5 CTAs/SM
// ============================================================
__global__ __launch_bounds__(BLOCK, 5)
void tq_main_kernel(const float* __restrict__ x,
                    const float* __restrict__ W,
                    const float* __restrict__ bias,
                    float* __restrict__ out) {
    __shared__ u64 ybuf[2][WPB][16 * 32];

    const int lane = threadIdx.x & 31;
    const int wid  = threadIdx.x >> 5;
    const int b    = blockIdx.x * WPB + wid;
    u64* b0 = ybuf[0][wid];
    u64* b1 = ybuf[1][wid];

    // per-qubit post-layer-0 2-vectors: v_q = (cos,-sin) @ M0_q
    float2 v0[NQ], v1[NQ];
    {
        float x0 = x[b*3+0], x1 = x[b*3+1], x2 = x[b*3+2];
#pragma unroll
        for (int q = 0; q < NQ; ++q) {
            float z = fmaf(x0, W[q*3+0], fmaf(x1, W[q*3+1], fmaf(x2, W[q*3+2], bias[q])));
            float t = 3.14159265358979323846f * tanhf(z);
            float s, c; sincosf(0.5f * t, &s, &c);
            const float* mm = &cM0[q * 8];
            v0[q].x = fmaf(c, mm[0], -s * mm[4]);
            v0[q].y = fmaf(c, mm[1], -s * mm[5]);
            v1[q].x = fmaf(c, mm[2], -s * mm[6]);
            v1[q].y = fmaf(c, mm[3], -s * mm[7]);
        }
    }

    // complex product-state build (gauge 0), ys -> bank 0
    u64 xs[16];
    {
        float2 F = (lane & 1) ? v1[9] : v0[9];
#pragma unroll
        for (int p = 1; p < 5; ++p) {
            float2 g = ((lane >> p) & 1) ? v1[9 - p] : v0[9 - p];
            F = make_float2(F.x * g.x - F.y * g.y, F.x * g.y + F.y * g.x);
        }
        float2 af[16];
        af[0] = F;
#pragma unroll
        for (int bit = 0; bit < 4; ++bit) {
            int q = 4 - bit;
#pragma unroll
            for (int k = (1 << bit) - 1; k >= 0; --k) {
                float2 a = af[k];
                af[k | (1 << bit)] = make_float2(a.x * v1[q].x - a.y * v1[q].y,
                                                 a.x * v1[q].y + a.y * v1[q].x);
                af[k]              = make_float2(a.x * v0[q].x - a.y * v0[q].y,
                                                 a.x * v0[q].y + a.y * v0[q].x);
            }
        }
#pragma unroll
        for (int j = 0; j < 16; ++j) {
            float2 a = af[j];
            float lox = a.x * v0[0].x - a.y * v0[0].y;
            float loy = a.x * v0[0].y + a.y * v0[0].x;
            float hix = a.x * v1[0].x - a.y * v1[0].y;
            float hiy = a.x * v1[0].y + a.y * v1[0].x;
            xs[j] = pk2(lox, hix);
            b0[j * 32 + lane] = pk2(loy, hiy);
        }
    }

    run_layers(xs, b0, b1, lane);

    __syncwarp();
    // packed probabilities into xs (final ys in bank 0; gauge cancels)
#pragma unroll
    for (int j = 0; j < 16; ++j) {
        u64 yv = b0[j * 32 + lane];
        xs[j] = fma2(yv, yv, mul2(xs[j], xs[j]));
    }

    float e[NQ];
    e[0] = readout_one<0>(xs, lane);
    e[1] = readout_one<1>(xs, lane);
    e[2] = readout_one<2>(xs, lane);
    e[3] = readout_one<3>(xs, lane);
    e[4] = readout_one<4>(xs, lane);
    e[5] = readout_one<5>(xs, lane);
    e[6] = readout_one<6>(xs, lane);
    e[7] = readout_one<7>(xs, lane);
    e[8] = readout_one<8>(xs, lane);
    e[9] = readout_one<9>(xs, lane);

    if (lane == 0) {
#pragma unroll
        for (int q = 0; q < NQ; ++q) out[b * NQ + q] = e[q];
    }
}

extern "C" void kernel_launch(void* const* d_in, const int* in_sizes, int n_in,
                              void* d_out, int out_size) {
    const float* x     = (const float*)d_in[0];   // [16384, 3]
    const float* enc_W = (const float*)d_in[1];   // [10, 3]
    const float* enc_b = (const float*)d_in[2];   // [10]
    const float* theta = (const float*)d_in[3];   // [4, 10, 3]
    float* out = (float*)d_out;                   // [16384, 10]

    int batch = in_sizes[0] / 3;

    // Maximize smem carveout so 5 CTAs x 32KB fit per SM.
    cudaFuncSetAttribute(tq_main_kernel,
                         cudaFuncAttributePreferredSharedMemoryCarveout, 100);

    tq_setup_kernel<<<1, 64>>>(theta);

    void* src = nullptr;
    cudaGetSymbolAddress(&src, gPackedBuf);
    cudaMemcpyToSymbolAsync(cG, src, sizeof(u64) * NL * NQ * 6, 0,
                            cudaMemcpyDeviceToDevice, 0);
    void* src0 = nullptr;
    cudaGetSymbolAddress(&src0, gM0Buf);
    cudaMemcpyToSymbolAsync(cM0, src0, sizeof(float) * NQ * 8, 0,
                            cudaMemcpyDeviceToDevice, 0);

    tq_main_kernel<<<batch / WPB, BLOCK>>>(x, enc_W, enc_b, out);
}